// round 6
// baseline (speedup 1.0000x reference)
#include <cuda_runtime.h>
#include <math.h>
#include <stdint.h>

// Problem constants
#define Bb   8
#define Nn   64
#define Dd   128
#define Hh   4
#define DHh  32
#define Llay 3
#define FFf  512
#define Mm   (Bb*Nn*Nn)   // 32768 tokens

// ---------------- scratch (device globals; no runtime allocation) ----------------
__device__ float g_tok[Mm*Dd];            // 16 MB
__device__ float g_q  [Mm*Dd];
__device__ float g_k  [Mm*Dd];
__device__ float g_v1 [Mm*Dd];
__device__ float g_v2 [Mm*Dd];
__device__ float g_s  [Bb*Hh*Nn*Nn*Nn];   // [b,h,l,i,j]  33.5 MB
__device__ float g_o  [Mm*Dd];
__device__ float g_hid[Mm*FFf];           // 64 MB

// ---------------- helpers ----------------
__device__ __forceinline__ void mma8(float* c, const uint32_t* a, uint32_t b0, uint32_t b1) {
    asm volatile("mma.sync.aligned.m16n8k8.row.col.f32.tf32.tf32.f32 "
                 "{%0,%1,%2,%3}, {%4,%5,%6,%7}, {%8,%9}, {%0,%1,%2,%3};"
                 : "+f"(c[0]), "+f"(c[1]), "+f"(c[2]), "+f"(c[3])
                 : "r"(a[0]), "r"(a[1]), "r"(a[2]), "r"(a[3]), "r"(b0), "r"(b1));
}
__device__ __forceinline__ void cp16(void* dst_smem, const void* src) {
    uint32_t d = (uint32_t)__cvta_generic_to_shared(dst_smem);
    asm volatile("cp.async.cg.shared.global [%0], [%1], 16;" :: "r"(d), "l"(src) : "memory");
}
__device__ __forceinline__ void cp4(void* dst_smem, const void* src) {
    uint32_t d = (uint32_t)__cvta_generic_to_shared(dst_smem);
    asm volatile("cp.async.ca.shared.global [%0], [%1], 4;" :: "r"(d), "l"(src) : "memory");
}
__device__ __forceinline__ void cp_commit() {
    asm volatile("cp.async.commit_group;" ::: "memory");
}
template<int N>
__device__ __forceinline__ void cp_wait() {
    asm volatile("cp.async.wait_group %0;" :: "n"(N) : "memory");
}

// ---------------- embedding ----------------
__global__ void embed_kernel(const float* __restrict__ x, const float* __restrict__ ea,
                             const int* __restrict__ mask,
                             const float* __restrict__ nW, const float* __restrict__ nb,
                             const float* __restrict__ eW, const float* __restrict__ eb,
                             const float* __restrict__ noe)
{
    int m = blockIdx.x;           // token index (b,i,j)
    int d = threadIdx.x;          // 0..127
    int b = m >> 12;
    int i = (m >> 6) & 63;
    int j = m & 63;
    __shared__ float in_s[16];
    if (i == j) {
        if (d < 16) in_s[d] = x[(b*64+i)*16 + d];
        __syncthreads();
        float acc = nb[d];
        #pragma unroll
        for (int k = 0; k < 16; k++) acc += in_s[k] * nW[k*128 + d];
        g_tok[(size_t)m*128 + d] = acc;
    } else if (mask[m] != 0) {
        if (d < 8) in_s[d] = ea[(size_t)m*8 + d];
        __syncthreads();
        float acc = eb[d];
        #pragma unroll
        for (int k = 0; k < 8; k++) acc += in_s[k] * eW[k*128 + d];
        g_tok[(size_t)m*128 + d] = acc;
    } else {
        g_tok[(size_t)m*128 + d] = noe[d];
    }
}

// ---------------- TF32 tensor-core GEMM: 128x128 CTA tile, BK=16, cp.async double-buffer ----------------
// 128 threads = 4 warps in 2(m) x 2(n); warp tile 64x64 via 4x8 m16n8k8 fragments.
// EPI: 0 = plain store, 1 = bias+relu store, 2 = fused residual+bias+LayerNorm into C (Ndim=128,n0=0)
template<int EPI>
__device__ __forceinline__ void mma_core(const float* __restrict__ A,
                                         const float* __restrict__ W,
                                         float* __restrict__ C,
                                         const float* __restrict__ bias,
                                         const float* __restrict__ gamma,
                                         const float* __restrict__ beta,
                                         int Ndim, int Kdim, int m0, int n0)
{
    __shared__ float As[2][128][20];   // [buf][m][k(16)+pad4] — frag loads conflict-free
    __shared__ float Bs[2][16][136];   // [buf][k][n(128)+pad8]
    __shared__ float ps[128][2], ps2[128][2], pmv[128], prv[128];

    const int t    = threadIdx.x;
    const int lane = t & 31;
    const int w    = t >> 5;
    const int wm   = w >> 1;            // 0..1
    const int wn   = w & 1;             // 0..1
    const int g    = lane >> 2;         // 0..7
    const int tig  = lane & 3;          // 0..3

    float c_[4][8][4];
    #pragma unroll
    for (int mi = 0; mi < 4; mi++)
        #pragma unroll
        for (int ni = 0; ni < 8; ni++)
            #pragma unroll
            for (int r = 0; r < 4; r++) c_[mi][ni][r] = 0.f;

    auto issue = [&](int kb, int buf) {
        #pragma unroll
        for (int q = 0; q < 4; q++) {          // A tile: 128 rows x 16k = 512 float4
            int idx = q*128 + t;
            int m = idx >> 2, f4 = idx & 3;
            cp16(&As[buf][m][f4*4], A + (size_t)(m0+m)*Kdim + kb*16 + f4*4);
        }
        #pragma unroll
        for (int q = 0; q < 4; q++) {          // B tile: 16k x 128n = 512 float4
            int idx = q*128 + t;
            int k = idx >> 5, n4 = idx & 31;
            cp16(&Bs[buf][k][n4*4], W + (size_t)(kb*16+k)*Ndim + n0 + n4*4);
        }
        cp_commit();
    };

    issue(0, 0);
    const int nk = Kdim >> 4;
    for (int kb = 0; kb < nk; kb++) {
        const int cur = kb & 1;
        cp_wait<0>();
        __syncthreads();
        if (kb + 1 < nk) issue(kb+1, cur ^ 1);

        #pragma unroll
        for (int k8 = 0; k8 < 16; k8 += 8) {
            uint32_t af[4][4];
            #pragma unroll
            for (int mi = 0; mi < 4; mi++) {
                int mm = wm*64 + mi*16 + g;
                af[mi][0] = __float_as_uint(As[cur][mm  ][k8+tig]);
                af[mi][1] = __float_as_uint(As[cur][mm+8][k8+tig]);
                af[mi][2] = __float_as_uint(As[cur][mm  ][k8+tig+4]);
                af[mi][3] = __float_as_uint(As[cur][mm+8][k8+tig+4]);
            }
            uint32_t bf[8][2];
            #pragma unroll
            for (int ni = 0; ni < 8; ni++) {
                int nn = wn*64 + ni*8 + g;
                bf[ni][0] = __float_as_uint(Bs[cur][k8+tig  ][nn]);
                bf[ni][1] = __float_as_uint(Bs[cur][k8+tig+4][nn]);
            }
            #pragma unroll
            for (int mi = 0; mi < 4; mi++)
                #pragma unroll
                for (int ni = 0; ni < 8; ni++)
                    mma8(c_[mi][ni], af[mi], bf[ni][0], bf[ni][1]);
        }
    }

    if (EPI == 2) {
        // fused residual + bias + LayerNorm; Ndim==128, n0==0, C == tok (also residual)
        float bi[8][2], gm[8][2], bt[8][2];
        #pragma unroll
        for (int ni = 0; ni < 8; ni++) {
            int col = wn*64 + ni*8 + 2*tig;
            float2 v;
            v = *(const float2*)(bias  + col); bi[ni][0] = v.x; bi[ni][1] = v.y;
            v = *(const float2*)(gamma + col); gm[ni][0] = v.x; gm[ni][1] = v.y;
            v = *(const float2*)(beta  + col); bt[ni][0] = v.x; bt[ni][1] = v.y;
        }
        #pragma unroll
        for (int mi = 0; mi < 4; mi++) {
            #pragma unroll
            for (int hh = 0; hh < 2; hh++) {
                int lrow = wm*64 + mi*16 + g + hh*8;
                size_t m = (size_t)(m0 + lrow);
                float s = 0.f, s2 = 0.f;
                #pragma unroll
                for (int ni = 0; ni < 8; ni++) {
                    int col = wn*64 + ni*8 + 2*tig;
                    float2 res = *(const float2*)(C + m*128 + col);
                    float v0 = c_[mi][ni][hh*2+0] + res.x + bi[ni][0];
                    float v1 = c_[mi][ni][hh*2+1] + res.y + bi[ni][1];
                    c_[mi][ni][hh*2+0] = v0;
                    c_[mi][ni][hh*2+1] = v1;
                    s += v0 + v1; s2 += v0*v0 + v1*v1;
                }
                // quad reduce over tig (lanes g*4+tig)
                s  += __shfl_xor_sync(0xffffffffu, s,  1);
                s  += __shfl_xor_sync(0xffffffffu, s,  2);
                s2 += __shfl_xor_sync(0xffffffffu, s2, 1);
                s2 += __shfl_xor_sync(0xffffffffu, s2, 2);
                if (tig == 0) { ps[lrow][wn] = s; ps2[lrow][wn] = s2; }
            }
        }
        __syncthreads();
        if (t < 128) {
            float s = ps[t][0] + ps[t][1];
            float s2 = ps2[t][0] + ps2[t][1];
            float mean = s * (1.f/128.f);
            float var  = s2 * (1.f/128.f) - mean*mean;
            pmv[t] = mean;
            prv[t] = rsqrtf(var + 1e-5f);
        }
        __syncthreads();
        #pragma unroll
        for (int mi = 0; mi < 4; mi++) {
            #pragma unroll
            for (int hh = 0; hh < 2; hh++) {
                int lrow = wm*64 + mi*16 + g + hh*8;
                size_t m = (size_t)(m0 + lrow);
                float mean = pmv[lrow], r = prv[lrow];
                #pragma unroll
                for (int ni = 0; ni < 8; ni++) {
                    int col = wn*64 + ni*8 + 2*tig;
                    float2 o;
                    o.x = (c_[mi][ni][hh*2+0] - mean) * r * gm[ni][0] + bt[ni][0];
                    o.y = (c_[mi][ni][hh*2+1] - mean) * r * gm[ni][1] + bt[ni][1];
                    *(float2*)(C + m*128 + col) = o;
                }
            }
        }
    } else {
        #pragma unroll
        for (int mi = 0; mi < 4; mi++) {
            #pragma unroll
            for (int hh = 0; hh < 2; hh++) {
                size_t m = (size_t)(m0 + wm*64 + mi*16 + g + hh*8);
                #pragma unroll
                for (int ni = 0; ni < 8; ni++) {
                    int col = n0 + wn*64 + ni*8 + 2*tig;
                    float v0 = c_[mi][ni][hh*2+0];
                    float v1 = c_[mi][ni][hh*2+1];
                    if (EPI == 1) {
                        v0 = fmaxf(v0 + bias[col],   0.f);
                        v1 = fmaxf(v1 + bias[col+1], 0.f);
                    }
                    float2 o; o.x = v0; o.y = v1;
                    *(float2*)(C + m * Ndim + col) = o;
                }
            }
        }
    }
}

struct Ptr8 { const float* w[4]; float* c[4]; };

__global__ void __launch_bounds__(128, 2) sgemm4_kernel(const float* A, Ptr8 p)
{
    mma_core<0>(A, p.w[blockIdx.z], p.c[blockIdx.z], nullptr, nullptr, nullptr,
                128, 128, blockIdx.y * 128, 0);
}
__global__ void __launch_bounds__(128, 2) sgemm_bias_relu_kernel(const float* A, const float* W,
                                                                 float* C, const float* bias,
                                                                 int Ndim, int Kdim)
{
    mma_core<1>(A, W, C, bias, nullptr, nullptr, Ndim, Kdim,
                blockIdx.y * 128, blockIdx.x * 128);
}
__global__ void __launch_bounds__(128, 2) sgemm_ln_kernel(const float* A, const float* W,
                                                          float* TOK, const float* bias,
                                                          const float* gamma, const float* beta,
                                                          int Kdim)
{
    mma_core<2>(A, W, TOK, bias, gamma, beta, 128, Kdim, blockIdx.y * 128, 0);
}

// ---------------- attention scores: s[b,h,l,i,j] = Q_l @ K_l^T / sqrt(DH) ----------------
__global__ void __launch_bounds__(256) scores_kernel()
{
    int lin = blockIdx.x;          // (b,h,l)
    int l = lin & 63, h = (lin >> 6) & 3, b = lin >> 8;
    __shared__ float Qs[32][68];   // [d][i]
    __shared__ float Ks[32][68];   // [d][j]
    for (int e = threadIdx.x; e < 2048; e += 256) {
        int i = e >> 5, d = e & 31;
        Qs[d][i] = g_q[((size_t)((b*64+i)*64 + l))*128 + h*32 + d];
        Ks[d][i] = g_k[((size_t)((b*64+l)*64 + i))*128 + h*32 + d];
    }
    __syncthreads();
    int ti = threadIdx.x >> 4, tj = threadIdx.x & 15;
    int i0 = ti*4, j0 = tj*4;
    float acc[4][4];
    #pragma unroll
    for (int a = 0; a < 4; a++)
        #pragma unroll
        for (int c = 0; c < 4; c++) acc[a][c] = 0.f;
    #pragma unroll
    for (int d = 0; d < 32; d++) {
        float4 ra = *(const float4*)&Qs[d][i0];
        float4 rb = *(const float4*)&Ks[d][j0];
        float A[4] = {ra.x, ra.y, ra.z, ra.w};
        float Bv[4] = {rb.x, rb.y, rb.z, rb.w};
        #pragma unroll
        for (int ii = 0; ii < 4; ii++)
            #pragma unroll
            for (int jj = 0; jj < 4; jj++)
                acc[ii][jj] += A[ii] * Bv[jj];
    }
    const float isc = 0.17677669529663687f;   // 1/sqrt(32)
    float* sp = g_s + ((size_t)((b*4+h)*64 + l)) * 4096;
    #pragma unroll
    for (int ii = 0; ii < 4; ii++) {
        float4 v = make_float4(acc[ii][0]*isc, acc[ii][1]*isc, acc[ii][2]*isc, acc[ii][3]*isc);
        *(float4*)(sp + (i0+ii)*64 + j0) = v;
    }
}

// ---------------- combine + fused softmax over l ----------------
// o[b,i,j,h,d] = sum_l softmax_l(s)[b,h,l,i,j] * v1[b,i,l,h,d] * v2[b,l,j,h,d]
// i-tiled by 4; v2 slice triple-buffered via cp.async ring; softmax done in-smem on raw scores.
// dyn smem: a4[4][64][64] | v1s[4][64][32] | v2s[3][64][33] | invs[4][64]
#define CMB_SMEM ((16384 + 8192 + 3*2112 + 256) * 4)
__global__ void __launch_bounds__(512) combine_kernel()
{
    extern __shared__ float smc[];
    float* a4   = smc;            // [ii*4096 + l*64 + j]  raw s -> exp(s - max)
    float* v1s  = smc + 16384;    // [ii*2048 + l*32 + d]
    float* v2s  = smc + 24576;    // [st*2112 + j*33 + d]
    float* invs = smc + 24576 + 3*2112;  // [ii*64 + j] = 1/sum

    int lin = blockIdx.x;        // (b,h,i4)
    int i4 = lin & 15, h = (lin >> 4) & 3, b = lin >> 6;
    int t = threadIdx.x;
    int j = t & 63, dg = t >> 6; // dg 0..7, 4 d's each

    const float* abase = g_s + ((size_t)(b*4+h))*262144;
    for (int e = t; e < 16384; e += 512) {
        int ii = e >> 12, l = (e >> 6) & 63, jj = e & 63;
        a4[ii*4096 + l*64 + jj] = abase[(size_t)l*4096 + (i4*4+ii)*64 + jj];
    }
    for (int e = t; e < 8192; e += 512) {
        int ii = e >> 11, l = (e >> 5) & 63, d = e & 31;
        v1s[ii*2048 + l*32 + d] = g_v1[((size_t)((b*64+i4*4+ii)*64 + l))*128 + h*32 + d];
    }

    auto issue_v2 = [&](int l, int st) {
        #pragma unroll
        for (int q = 0; q < 4; q++) {
            int e = q*512 + t;            // 2048 floats
            int jj = e >> 5, d = e & 31;
            cp4(&v2s[st*2112 + jj*33 + d],
                g_v2 + ((size_t)((b*64+l)*64 + jj))*128 + h*32 + d);
        }
        cp_commit();
    };

    // start v2 pipeline before softmax so DRAM latency overlaps softmax compute
    issue_v2(0, 0);
    issue_v2(1, 1);
    __syncthreads();   // a4/v1s visible to all

    // ---- softmax over l for each (ii, j): 2 threads per column (halves of l) ----
    {
        int col = t >> 1, half = t & 1;     // col 0..255
        int cii = col >> 6, cj = col & 63;
        float* sp = a4 + cii*4096 + cj + half*32*64;
        float mx = -1e30f;
        #pragma unroll 4
        for (int l = 0; l < 32; l++) mx = fmaxf(mx, sp[l*64]);
        mx = fmaxf(mx, __shfl_xor_sync(0xffffffffu, mx, 1));
        float sum = 0.f;
        #pragma unroll 4
        for (int l = 0; l < 32; l++) { float e = __expf(sp[l*64] - mx); sp[l*64] = e; sum += e; }
        sum += __shfl_xor_sync(0xffffffffu, sum, 1);
        if (half == 0) invs[col] = 1.f / sum;
    }
    __syncthreads();

    float inv4[4];
    #pragma unroll
    for (int ii = 0; ii < 4; ii++) inv4[ii] = invs[ii*64 + j];

    float acc[4][4];
    #pragma unroll
    for (int ii = 0; ii < 4; ii++)
        #pragma unroll
        for (int k = 0; k < 4; k++) acc[ii][k] = 0.f;

    for (int l = 0; l < 64; l++) {
        if (l < 62) cp_wait<1>(); else cp_wait<0>();
        __syncthreads();
        if (l + 2 < 64) issue_v2(l+2, (l+2) % 3);
        int ls = (l % 3) * 2112;
        float v2r[4];
        #pragma unroll
        for (int k = 0; k < 4; k++) v2r[k] = v2s[ls + j*33 + dg*4 + k];
        #pragma unroll
        for (int ii = 0; ii < 4; ii++) {
            float av = a4[ii*4096 + l*64 + j];
            const float* v1p = &v1s[ii*2048 + l*32 + dg*4];
            #pragma unroll
            for (int k = 0; k < 4; k++) acc[ii][k] += av * v1p[k] * v2r[k];
        }
    }
    #pragma unroll
    for (int ii = 0; ii < 4; ii++) {
        int i = i4*4 + ii;
        float4 v = make_float4(acc[ii][0]*inv4[ii], acc[ii][1]*inv4[ii],
                               acc[ii][2]*inv4[ii], acc[ii][3]*inv4[ii]);
        *(float4*)(g_o + ((size_t)((b*64+i)*64 + j))*128 + h*32 + dg*4) = v;
    }
}

// ---------------- final head: out[b,n] = tok[b,n,n,:] @ Wout + bout ----------------
__global__ void out_kernel(const float* __restrict__ Wout, const float* __restrict__ bout,
                           float* __restrict__ out)
{
    int bn = blockIdx.x, d = threadIdx.x;
    int b = bn >> 6, n = bn & 63;
    float v = g_tok[((size_t)((b*64+n)*64 + n))*128 + d] * Wout[d];
    #pragma unroll
    for (int o = 16; o; o >>= 1) v += __shfl_xor_sync(0xffffffffu, v, o);
    __shared__ float ws[4];
    if ((d & 31) == 0) ws[d >> 5] = v;
    __syncthreads();
    if (d == 0) out[bn] = ws[0] + ws[1] + ws[2] + ws[3] + bout[0];
}

// ---------------- host orchestration ----------------
extern "C" void kernel_launch(void* const* d_in, const int* in_sizes, int n_in,
                              void* d_out, int out_size)
{
    const float* x    = (const float*)d_in[0];
    const float* ea   = (const float*)d_in[1];
    const int*   mask = (const int*)d_in[2];
    const float* nW   = (const float*)d_in[3];
    const float* nb   = (const float*)d_in[4];
    const float* eW   = (const float*)d_in[5];
    const float* eb   = (const float*)d_in[6];
    const float* noe  = (const float*)d_in[7];
    const float* Wq   = (const float*)d_in[8];
    const float* Wk   = (const float*)d_in[9];
    const float* Wv1  = (const float*)d_in[10];
    const float* Wv2  = (const float*)d_in[11];
    const float* Wo   = (const float*)d_in[12];
    const float* bo   = (const float*)d_in[13];
    const float* ln1g = (const float*)d_in[14];
    const float* ln1b = (const float*)d_in[15];
    const float* W1   = (const float*)d_in[16];
    const float* b1   = (const float*)d_in[17];
    const float* W2   = (const float*)d_in[18];
    const float* b2   = (const float*)d_in[19];
    const float* ln2g = (const float*)d_in[20];
    const float* ln2b = (const float*)d_in[21];
    const float* Wout = (const float*)d_in[22];
    const float* bout = (const float*)d_in[23];
    float* out = (float*)d_out;

    float *tok, *q, *k, *v1, *v2, *o, *hid;
    cudaGetSymbolAddress((void**)&tok, g_tok);
    cudaGetSymbolAddress((void**)&q,   g_q);
    cudaGetSymbolAddress((void**)&k,   g_k);
    cudaGetSymbolAddress((void**)&v1,  g_v1);
    cudaGetSymbolAddress((void**)&v2,  g_v2);
    cudaGetSymbolAddress((void**)&o,   g_o);
    cudaGetSymbolAddress((void**)&hid, g_hid);

    cudaFuncSetAttribute(combine_kernel, cudaFuncAttributeMaxDynamicSharedMemorySize, CMB_SMEM);

    embed_kernel<<<Mm, 128>>>(x, ea, mask, nW, nb, eW, eb, noe);

    for (int l = 0; l < Llay; l++) {
        Ptr8 p;
        p.w[0] = Wq  + (size_t)l*128*128;
        p.w[1] = Wk  + (size_t)l*128*128;
        p.w[2] = Wv1 + (size_t)l*128*128;
        p.w[3] = Wv2 + (size_t)l*128*128;
        p.c[0] = q; p.c[1] = k; p.c[2] = v1; p.c[3] = v2;
        sgemm4_kernel<<<dim3(1, Mm/128, 4), 128>>>(tok, p);

        scores_kernel <<<Bb*Hh*Nn, 256>>>();
        combine_kernel<<<Bb*Hh*(Nn/4), 512, CMB_SMEM>>>();

        // tok = LN(tok + o@Wo + bo)   (fused epilogue)
        sgemm_ln_kernel<<<dim3(1, Mm/128), 128>>>(o, Wo + (size_t)l*128*128, tok,
                                                  bo + l*128, ln1g + l*128, ln1b + l*128, 128);

        // ff
        sgemm_bias_relu_kernel<<<dim3(FFf/128, Mm/128), 128>>>(tok, W1 + (size_t)l*128*512,
                                                               hid, b1 + l*512, 512, 128);
        // tok = LN(tok + hid@W2 + b2) (fused epilogue)
        sgemm_ln_kernel<<<dim3(1, Mm/128), 128>>>(hid, W2 + (size_t)l*512*128, tok,
                                                  b2 + l*128, ln2g + l*128, ln2b + l*128, 512);
    }

    out_kernel<<<Bb*Nn, 128>>>(Wout, bout, out);
}

// round 7
// speedup vs baseline: 1.3199x; 1.3199x over previous
#include <cuda_runtime.h>
#include <math.h>
#include <stdint.h>

// Problem constants
#define Bb   8
#define Nn   64
#define Dd   128
#define Hh   4
#define DHh  32
#define Llay 3
#define FFf  512
#define Mm   (Bb*Nn*Nn)   // 32768 tokens

// ---------------- scratch (device globals; no runtime allocation) ----------------
__device__ float g_tok[Mm*Dd];            // 16 MB
__device__ float g_q  [Mm*Dd];
__device__ float g_k  [Mm*Dd];
__device__ float g_v1 [Mm*Dd];
__device__ float g_v2 [Mm*Dd];
__device__ float g_s  [Bb*Hh*Nn*Nn*Nn];   // [b,h,l,i,j]  33.5 MB
__device__ float g_o  [Mm*Dd];
__device__ float g_hid[Mm*FFf];           // 64 MB

// ---------------- helpers ----------------
__device__ __forceinline__ void mma8(float* c, const uint32_t* a, uint32_t b0, uint32_t b1) {
    asm volatile("mma.sync.aligned.m16n8k8.row.col.f32.tf32.tf32.f32 "
                 "{%0,%1,%2,%3}, {%4,%5,%6,%7}, {%8,%9}, {%0,%1,%2,%3};"
                 : "+f"(c[0]), "+f"(c[1]), "+f"(c[2]), "+f"(c[3])
                 : "r"(a[0]), "r"(a[1]), "r"(a[2]), "r"(a[3]), "r"(b0), "r"(b1));
}
__device__ __forceinline__ void cp16(void* dst_smem, const void* src) {
    uint32_t d = (uint32_t)__cvta_generic_to_shared(dst_smem);
    asm volatile("cp.async.cg.shared.global [%0], [%1], 16;" :: "r"(d), "l"(src) : "memory");
}
__device__ __forceinline__ void cp_commit() {
    asm volatile("cp.async.commit_group;" ::: "memory");
}
template<int N>
__device__ __forceinline__ void cp_wait() {
    asm volatile("cp.async.wait_group %0;" :: "n"(N) : "memory");
}

// ---------------- embedding ----------------
__global__ void embed_kernel(const float* __restrict__ x, const float* __restrict__ ea,
                             const int* __restrict__ mask,
                             const float* __restrict__ nW, const float* __restrict__ nb,
                             const float* __restrict__ eW, const float* __restrict__ eb,
                             const float* __restrict__ noe)
{
    int m = blockIdx.x;           // token index (b,i,j)
    int d = threadIdx.x;          // 0..127
    int b = m >> 12;
    int i = (m >> 6) & 63;
    int j = m & 63;
    __shared__ float in_s[16];
    if (i == j) {
        if (d < 16) in_s[d] = x[(b*64+i)*16 + d];
        __syncthreads();
        float acc = nb[d];
        #pragma unroll
        for (int k = 0; k < 16; k++) acc += in_s[k] * nW[k*128 + d];
        g_tok[(size_t)m*128 + d] = acc;
    } else if (mask[m] != 0) {
        if (d < 8) in_s[d] = ea[(size_t)m*8 + d];
        __syncthreads();
        float acc = eb[d];
        #pragma unroll
        for (int k = 0; k < 8; k++) acc += in_s[k] * eW[k*128 + d];
        g_tok[(size_t)m*128 + d] = acc;
    } else {
        g_tok[(size_t)m*128 + d] = noe[d];
    }
}

// ---------------- TF32 tensor-core GEMM: 128x128 CTA tile, BK=16, cp.async double-buffer ----------------
// 128 threads = 4 warps in 2(m) x 2(n); warp tile 64x64 via 4x8 m16n8k8 fragments.
// EPI: 0 = plain store, 1 = bias+relu store, 2 = fused residual+bias+LayerNorm into C (Ndim=128,n0=0)
template<int EPI>
__device__ __forceinline__ void mma_core(const float* __restrict__ A,
                                         const float* __restrict__ W,
                                         float* __restrict__ C,
                                         const float* __restrict__ bias,
                                         const float* __restrict__ gamma,
                                         const float* __restrict__ beta,
                                         int Ndim, int Kdim, int m0, int n0)
{
    __shared__ float As[2][128][20];   // [buf][m][k(16)+pad4] — frag loads conflict-free
    __shared__ float Bs[2][16][136];   // [buf][k][n(128)+pad8]
    __shared__ float ps[128][2], ps2[128][2], pmv[128], prv[128];

    const int t    = threadIdx.x;
    const int lane = t & 31;
    const int w    = t >> 5;
    const int wm   = w >> 1;            // 0..1
    const int wn   = w & 1;             // 0..1
    const int g    = lane >> 2;         // 0..7
    const int tig  = lane & 3;          // 0..3

    float c_[4][8][4];
    #pragma unroll
    for (int mi = 0; mi < 4; mi++)
        #pragma unroll
        for (int ni = 0; ni < 8; ni++)
            #pragma unroll
            for (int r = 0; r < 4; r++) c_[mi][ni][r] = 0.f;

    auto issue = [&](int kb, int buf) {
        #pragma unroll
        for (int q = 0; q < 4; q++) {          // A tile: 128 rows x 16k = 512 float4
            int idx = q*128 + t;
            int m = idx >> 2, f4 = idx & 3;
            cp16(&As[buf][m][f4*4], A + (size_t)(m0+m)*Kdim + kb*16 + f4*4);
        }
        #pragma unroll
        for (int q = 0; q < 4; q++) {          // B tile: 16k x 128n = 512 float4
            int idx = q*128 + t;
            int k = idx >> 5, n4 = idx & 31;
            cp16(&Bs[buf][k][n4*4], W + (size_t)(kb*16+k)*Ndim + n0 + n4*4);
        }
        cp_commit();
    };

    issue(0, 0);
    const int nk = Kdim >> 4;
    for (int kb = 0; kb < nk; kb++) {
        const int cur = kb & 1;
        cp_wait<0>();
        __syncthreads();
        if (kb + 1 < nk) issue(kb+1, cur ^ 1);

        #pragma unroll
        for (int k8 = 0; k8 < 16; k8 += 8) {
            uint32_t af[4][4];
            #pragma unroll
            for (int mi = 0; mi < 4; mi++) {
                int mm = wm*64 + mi*16 + g;
                af[mi][0] = __float_as_uint(As[cur][mm  ][k8+tig]);
                af[mi][1] = __float_as_uint(As[cur][mm+8][k8+tig]);
                af[mi][2] = __float_as_uint(As[cur][mm  ][k8+tig+4]);
                af[mi][3] = __float_as_uint(As[cur][mm+8][k8+tig+4]);
            }
            uint32_t bf[8][2];
            #pragma unroll
            for (int ni = 0; ni < 8; ni++) {
                int nn = wn*64 + ni*8 + g;
                bf[ni][0] = __float_as_uint(Bs[cur][k8+tig  ][nn]);
                bf[ni][1] = __float_as_uint(Bs[cur][k8+tig+4][nn]);
            }
            #pragma unroll
            for (int mi = 0; mi < 4; mi++)
                #pragma unroll
                for (int ni = 0; ni < 8; ni++)
                    mma8(c_[mi][ni], af[mi], bf[ni][0], bf[ni][1]);
        }
    }

    if (EPI == 2) {
        // fused residual + bias + LayerNorm; Ndim==128, n0==0, C == tok (also residual)
        float bi[8][2], gm[8][2], bt[8][2];
        #pragma unroll
        for (int ni = 0; ni < 8; ni++) {
            int col = wn*64 + ni*8 + 2*tig;
            float2 v;
            v = *(const float2*)(bias  + col); bi[ni][0] = v.x; bi[ni][1] = v.y;
            v = *(const float2*)(gamma + col); gm[ni][0] = v.x; gm[ni][1] = v.y;
            v = *(const float2*)(beta  + col); bt[ni][0] = v.x; bt[ni][1] = v.y;
        }
        #pragma unroll
        for (int mi = 0; mi < 4; mi++) {
            #pragma unroll
            for (int hh = 0; hh < 2; hh++) {
                int lrow = wm*64 + mi*16 + g + hh*8;
                size_t m = (size_t)(m0 + lrow);
                float s = 0.f, s2 = 0.f;
                #pragma unroll
                for (int ni = 0; ni < 8; ni++) {
                    int col = wn*64 + ni*8 + 2*tig;
                    float2 res = *(const float2*)(C + m*128 + col);
                    float v0 = c_[mi][ni][hh*2+0] + res.x + bi[ni][0];
                    float v1 = c_[mi][ni][hh*2+1] + res.y + bi[ni][1];
                    c_[mi][ni][hh*2+0] = v0;
                    c_[mi][ni][hh*2+1] = v1;
                    s += v0 + v1; s2 += v0*v0 + v1*v1;
                }
                // quad reduce over tig (lanes g*4+tig)
                s  += __shfl_xor_sync(0xffffffffu, s,  1);
                s  += __shfl_xor_sync(0xffffffffu, s,  2);
                s2 += __shfl_xor_sync(0xffffffffu, s2, 1);
                s2 += __shfl_xor_sync(0xffffffffu, s2, 2);
                if (tig == 0) { ps[lrow][wn] = s; ps2[lrow][wn] = s2; }
            }
        }
        __syncthreads();
        if (t < 128) {
            float s = ps[t][0] + ps[t][1];
            float s2 = ps2[t][0] + ps2[t][1];
            float mean = s * (1.f/128.f);
            float var  = s2 * (1.f/128.f) - mean*mean;
            pmv[t] = mean;
            prv[t] = rsqrtf(var + 1e-5f);
        }
        __syncthreads();
        #pragma unroll
        for (int mi = 0; mi < 4; mi++) {
            #pragma unroll
            for (int hh = 0; hh < 2; hh++) {
                int lrow = wm*64 + mi*16 + g + hh*8;
                size_t m = (size_t)(m0 + lrow);
                float mean = pmv[lrow], r = prv[lrow];
                #pragma unroll
                for (int ni = 0; ni < 8; ni++) {
                    int col = wn*64 + ni*8 + 2*tig;
                    float2 o;
                    o.x = (c_[mi][ni][hh*2+0] - mean) * r * gm[ni][0] + bt[ni][0];
                    o.y = (c_[mi][ni][hh*2+1] - mean) * r * gm[ni][1] + bt[ni][1];
                    *(float2*)(C + m*128 + col) = o;
                }
            }
        }
    } else {
        #pragma unroll
        for (int mi = 0; mi < 4; mi++) {
            #pragma unroll
            for (int hh = 0; hh < 2; hh++) {
                size_t m = (size_t)(m0 + wm*64 + mi*16 + g + hh*8);
                #pragma unroll
                for (int ni = 0; ni < 8; ni++) {
                    int col = n0 + wn*64 + ni*8 + 2*tig;
                    float v0 = c_[mi][ni][hh*2+0];
                    float v1 = c_[mi][ni][hh*2+1];
                    if (EPI == 1) {
                        v0 = fmaxf(v0 + bias[col],   0.f);
                        v1 = fmaxf(v1 + bias[col+1], 0.f);
                    }
                    float2 o; o.x = v0; o.y = v1;
                    *(float2*)(C + m * Ndim + col) = o;
                }
            }
        }
    }
}

struct Ptr8 { const float* w[4]; float* c[4]; };

__global__ void __launch_bounds__(128, 2) sgemm4_kernel(const float* A, Ptr8 p)
{
    mma_core<0>(A, p.w[blockIdx.z], p.c[blockIdx.z], nullptr, nullptr, nullptr,
                128, 128, blockIdx.y * 128, 0);
}
__global__ void __launch_bounds__(128, 2) sgemm_bias_relu_kernel(const float* A, const float* W,
                                                                 float* C, const float* bias,
                                                                 int Ndim, int Kdim)
{
    mma_core<1>(A, W, C, bias, nullptr, nullptr, Ndim, Kdim,
                blockIdx.y * 128, blockIdx.x * 128);
}
__global__ void __launch_bounds__(128, 2) sgemm_ln_kernel(const float* A, const float* W,
                                                          float* TOK, const float* bias,
                                                          const float* gamma, const float* beta,
                                                          int Kdim)
{
    mma_core<2>(A, W, TOK, bias, gamma, beta, 128, Kdim, blockIdx.y * 128, 0);
}

// ---------------- attention scores: s[b,h,l,i,j] = Q_l @ K_l^T / sqrt(DH) ----------------
__global__ void __launch_bounds__(256) scores_kernel()
{
    int lin = blockIdx.x;          // (b,h,l)
    int l = lin & 63, h = (lin >> 6) & 3, b = lin >> 8;
    __shared__ float Qs[32][68];   // [d][i]
    __shared__ float Ks[32][68];   // [d][j]
    for (int e = threadIdx.x; e < 2048; e += 256) {
        int i = e >> 5, d = e & 31;
        Qs[d][i] = g_q[((size_t)((b*64+i)*64 + l))*128 + h*32 + d];
        Ks[d][i] = g_k[((size_t)((b*64+l)*64 + i))*128 + h*32 + d];
    }
    __syncthreads();
    int ti = threadIdx.x >> 4, tj = threadIdx.x & 15;
    int i0 = ti*4, j0 = tj*4;
    float acc[4][4];
    #pragma unroll
    for (int a = 0; a < 4; a++)
        #pragma unroll
        for (int c = 0; c < 4; c++) acc[a][c] = 0.f;
    #pragma unroll
    for (int d = 0; d < 32; d++) {
        float4 ra = *(const float4*)&Qs[d][i0];
        float4 rb = *(const float4*)&Ks[d][j0];
        float A[4] = {ra.x, ra.y, ra.z, ra.w};
        float Bv[4] = {rb.x, rb.y, rb.z, rb.w};
        #pragma unroll
        for (int ii = 0; ii < 4; ii++)
            #pragma unroll
            for (int jj = 0; jj < 4; jj++)
                acc[ii][jj] += A[ii] * Bv[jj];
    }
    const float isc = 0.17677669529663687f;   // 1/sqrt(32)
    float* sp = g_s + ((size_t)((b*4+h)*64 + l)) * 4096;
    #pragma unroll
    for (int ii = 0; ii < 4; ii++) {
        float4 v = make_float4(acc[ii][0]*isc, acc[ii][1]*isc, acc[ii][2]*isc, acc[ii][3]*isc);
        *(float4*)(sp + (i0+ii)*64 + j0) = v;
    }
}

// ---------------- combine + fused softmax over l ----------------
// o[b,i,j,h,d] = sum_l softmax_l(s)[b,h,l,i,j] * v1[b,i,l,h,d] * v2[b,l,j,h,d]
// i-tiled by 4. Thread map: t = j*8 + dg (j=t>>3, dg=t&7, 4 d's each).
// v2 read DIRECTLY from gmem (L2) as coalesced float4 with register prefetch — no ring, no per-l barriers.
// dyn smem: a4[4][64][64] | v1s[4][64][32] | invs[4][64]
#define CMB_SMEM ((16384 + 8192 + 256) * 4)
__global__ void __launch_bounds__(512, 2) combine_kernel()
{
    extern __shared__ float smc[];
    float* a4   = smc;            // [ii*4096 + l*64 + j]  raw s -> exp(s - max)
    float* v1s  = smc + 16384;    // [ii*2048 + l*32 + d]
    float* invs = smc + 24576;    // [ii*64 + j] = 1/sum

    int lin = blockIdx.x;        // (b,h,i4)
    int i4 = lin & 15, h = (lin >> 4) & 3, b = lin >> 6;
    int t = threadIdx.x;
    int j = t >> 3, dg = t & 7;  // dg 0..7, 4 d's each

    const float* abase = g_s + ((size_t)(b*4+h))*262144;
    for (int e = t; e < 16384; e += 512) {
        int ii = e >> 12, l = (e >> 6) & 63, jj = e & 63;
        a4[ii*4096 + l*64 + jj] = abase[(size_t)l*4096 + (i4*4+ii)*64 + jj];
    }
    for (int e = t; e < 8192; e += 512) {
        int ii = e >> 11, l = (e >> 5) & 63, d = e & 31;
        v1s[ii*2048 + l*32 + d] = g_v1[((size_t)((b*64+i4*4+ii)*64 + l))*128 + h*32 + d];
    }
    __syncthreads();   // a4/v1s visible

    // ---- softmax over l for each (ii, j): 2 threads per column (halves of l) ----
    {
        int col = t >> 1, half = t & 1;     // col 0..255
        int cii = col >> 6, cj = col & 63;
        float* sp = a4 + cii*4096 + cj + half*32*64;
        float mx = -1e30f;
        #pragma unroll 4
        for (int l = 0; l < 32; l++) mx = fmaxf(mx, sp[l*64]);
        mx = fmaxf(mx, __shfl_xor_sync(0xffffffffu, mx, 1));
        float sum = 0.f;
        #pragma unroll 4
        for (int l = 0; l < 32; l++) { float e = __expf(sp[l*64] - mx); sp[l*64] = e; sum += e; }
        sum += __shfl_xor_sync(0xffffffffu, sum, 1);
        if (half == 0) invs[col] = 1.f / sum;
    }
    __syncthreads();

    float inv4[4];
    #pragma unroll
    for (int ii = 0; ii < 4; ii++) inv4[ii] = invs[ii*64 + j];

    float acc[4][4];
    #pragma unroll
    for (int ii = 0; ii < 4; ii++)
        #pragma unroll
        for (int k = 0; k < 4; k++) acc[ii][k] = 0.f;

    // v2 pointer for this thread's (j, dg): advance by l (stride 64*128 floats)
    const float* v2p = g_v2 + ((size_t)(b*64)*64 + j)*128 + h*32 + dg*4;
    const size_t v2step = (size_t)64*128;

    float4 nv = *(const float4*)(v2p);      // prefetch l=0
    for (int l = 0; l < 64; l++) {
        float4 v2r = nv;
        if (l + 1 < 64) nv = *(const float4*)(v2p + (size_t)(l+1)*v2step);
        float vr[4] = {v2r.x, v2r.y, v2r.z, v2r.w};
        #pragma unroll
        for (int ii = 0; ii < 4; ii++) {
            float av = a4[ii*4096 + l*64 + j];
            const float4 v1v = *(const float4*)&v1s[ii*2048 + l*32 + dg*4];
            acc[ii][0] += av * v1v.x * vr[0];
            acc[ii][1] += av * v1v.y * vr[1];
            acc[ii][2] += av * v1v.z * vr[2];
            acc[ii][3] += av * v1v.w * vr[3];
        }
    }
    #pragma unroll
    for (int ii = 0; ii < 4; ii++) {
        int i = i4*4 + ii;
        float4 v = make_float4(acc[ii][0]*inv4[ii], acc[ii][1]*inv4[ii],
                               acc[ii][2]*inv4[ii], acc[ii][3]*inv4[ii]);
        *(float4*)(g_o + ((size_t)((b*64+i)*64 + j))*128 + h*32 + dg*4) = v;
    }
}

// ---------------- final head: out[b,n] = tok[b,n,n,:] @ Wout + bout ----------------
__global__ void out_kernel(const float* __restrict__ Wout, const float* __restrict__ bout,
                           float* __restrict__ out)
{
    int bn = blockIdx.x, d = threadIdx.x;
    int b = bn >> 6, n = bn & 63;
    float v = g_tok[((size_t)((b*64+n)*64 + n))*128 + d] * Wout[d];
    #pragma unroll
    for (int o = 16; o; o >>= 1) v += __shfl_xor_sync(0xffffffffu, v, o);
    __shared__ float ws[4];
    if ((d & 31) == 0) ws[d >> 5] = v;
    __syncthreads();
    if (d == 0) out[bn] = ws[0] + ws[1] + ws[2] + ws[3] + bout[0];
}

// ---------------- host orchestration ----------------
extern "C" void kernel_launch(void* const* d_in, const int* in_sizes, int n_in,
                              void* d_out, int out_size)
{
    const float* x    = (const float*)d_in[0];
    const float* ea   = (const float*)d_in[1];
    const int*   mask = (const int*)d_in[2];
    const float* nW   = (const float*)d_in[3];
    const float* nb   = (const float*)d_in[4];
    const float* eW   = (const float*)d_in[5];
    const float* eb   = (const float*)d_in[6];
    const float* noe  = (const float*)d_in[7];
    const float* Wq   = (const float*)d_in[8];
    const float* Wk   = (const float*)d_in[9];
    const float* Wv1  = (const float*)d_in[10];
    const float* Wv2  = (const float*)d_in[11];
    const float* Wo   = (const float*)d_in[12];
    const float* bo   = (const float*)d_in[13];
    const float* ln1g = (const float*)d_in[14];
    const float* ln1b = (const float*)d_in[15];
    const float* W1   = (const float*)d_in[16];
    const float* b1   = (const float*)d_in[17];
    const float* W2   = (const float*)d_in[18];
    const float* b2   = (const float*)d_in[19];
    const float* ln2g = (const float*)d_in[20];
    const float* ln2b = (const float*)d_in[21];
    const float* Wout = (const float*)d_in[22];
    const float* bout = (const float*)d_in[23];
    float* out = (float*)d_out;

    float *tok, *q, *k, *v1, *v2, *o, *hid;
    cudaGetSymbolAddress((void**)&tok, g_tok);
    cudaGetSymbolAddress((void**)&q,   g_q);
    cudaGetSymbolAddress((void**)&k,   g_k);
    cudaGetSymbolAddress((void**)&v1,  g_v1);
    cudaGetSymbolAddress((void**)&v2,  g_v2);
    cudaGetSymbolAddress((void**)&o,   g_o);
    cudaGetSymbolAddress((void**)&hid, g_hid);

    cudaFuncSetAttribute(combine_kernel, cudaFuncAttributeMaxDynamicSharedMemorySize, CMB_SMEM);

    embed_kernel<<<Mm, 128>>>(x, ea, mask, nW, nb, eW, eb, noe);

    for (int l = 0; l < Llay; l++) {
        Ptr8 p;
        p.w[0] = Wq  + (size_t)l*128*128;
        p.w[1] = Wk  + (size_t)l*128*128;
        p.w[2] = Wv1 + (size_t)l*128*128;
        p.w[3] = Wv2 + (size_t)l*128*128;
        p.c[0] = q; p.c[1] = k; p.c[2] = v1; p.c[3] = v2;
        sgemm4_kernel<<<dim3(1, Mm/128, 4), 128>>>(tok, p);

        scores_kernel <<<Bb*Hh*Nn, 256>>>();
        combine_kernel<<<Bb*Hh*(Nn/4), 512, CMB_SMEM>>>();

        // tok = LN(tok + o@Wo + bo)   (fused epilogue)
        sgemm_ln_kernel<<<dim3(1, Mm/128), 128>>>(o, Wo + (size_t)l*128*128, tok,
                                                  bo + l*128, ln1g + l*128, ln1b + l*128, 128);

        // ff
        sgemm_bias_relu_kernel<<<dim3(FFf/128, Mm/128), 128>>>(tok, W1 + (size_t)l*128*512,
                                                               hid, b1 + l*512, 512, 128);
        // tok = LN(tok + hid@W2 + b2) (fused epilogue)
        sgemm_ln_kernel<<<dim3(1, Mm/128), 128>>>(hid, W2 + (size_t)l*512*128, tok,
                                                  b2 + l*128, ln2g + l*128, ln2b + l*128, 512);
    }

    out_kernel<<<Bb*Nn, 128>>>(Wout, bout, out);
}

// round 8
// speedup vs baseline: 1.4015x; 1.0618x over previous
#include <cuda_runtime.h>
#include <math.h>
#include <stdint.h>

// Problem constants
#define Bb   8
#define Nn   64
#define Dd   128
#define Hh   4
#define DHh  32
#define Llay 3
#define FFf  512
#define Mm   (Bb*Nn*Nn)   // 32768 tokens

// ---------------- scratch (device globals; no runtime allocation) ----------------
__device__ float g_tok[Mm*Dd];            // 16 MB
__device__ float g_q  [Mm*Dd];
__device__ float g_k  [Mm*Dd];
__device__ float g_v1 [Mm*Dd];
__device__ float g_v2 [Mm*Dd];
__device__ float g_s  [Bb*Hh*Nn*Nn*Nn];   // [b,h,l,i,j]  33.5 MB
__device__ float g_o  [Mm*Dd];
__device__ float g_hid[Mm*FFf];           // 64 MB

// ---------------- helpers ----------------
__device__ __forceinline__ void mma8(float* c, const uint32_t* a, uint32_t b0, uint32_t b1) {
    asm volatile("mma.sync.aligned.m16n8k8.row.col.f32.tf32.tf32.f32 "
                 "{%0,%1,%2,%3}, {%4,%5,%6,%7}, {%8,%9}, {%0,%1,%2,%3};"
                 : "+f"(c[0]), "+f"(c[1]), "+f"(c[2]), "+f"(c[3])
                 : "r"(a[0]), "r"(a[1]), "r"(a[2]), "r"(a[3]), "r"(b0), "r"(b1));
}
__device__ __forceinline__ void cp16(void* dst_smem, const void* src) {
    uint32_t d = (uint32_t)__cvta_generic_to_shared(dst_smem);
    asm volatile("cp.async.cg.shared.global [%0], [%1], 16;" :: "r"(d), "l"(src) : "memory");
}
__device__ __forceinline__ void cp_commit() {
    asm volatile("cp.async.commit_group;" ::: "memory");
}
template<int N>
__device__ __forceinline__ void cp_wait() {
    asm volatile("cp.async.wait_group %0;" :: "n"(N) : "memory");
}

// ---------------- embedding ----------------
__global__ void embed_kernel(const float* __restrict__ x, const float* __restrict__ ea,
                             const int* __restrict__ mask,
                             const float* __restrict__ nW, const float* __restrict__ nb,
                             const float* __restrict__ eW, const float* __restrict__ eb,
                             const float* __restrict__ noe)
{
    int m = blockIdx.x;           // token index (b,i,j)
    int d = threadIdx.x;          // 0..127
    int b = m >> 12;
    int i = (m >> 6) & 63;
    int j = m & 63;
    __shared__ float in_s[16];
    if (i == j) {
        if (d < 16) in_s[d] = x[(b*64+i)*16 + d];
        __syncthreads();
        float acc = nb[d];
        #pragma unroll
        for (int k = 0; k < 16; k++) acc += in_s[k] * nW[k*128 + d];
        g_tok[(size_t)m*128 + d] = acc;
    } else if (mask[m] != 0) {
        if (d < 8) in_s[d] = ea[(size_t)m*8 + d];
        __syncthreads();
        float acc = eb[d];
        #pragma unroll
        for (int k = 0; k < 8; k++) acc += in_s[k] * eW[k*128 + d];
        g_tok[(size_t)m*128 + d] = acc;
    } else {
        g_tok[(size_t)m*128 + d] = noe[d];
    }
}

// ---------------- TF32 tensor-core GEMM: 128x128 CTA tile, BK=32, cp.async double-buffer ----------------
// 128 threads = 4 warps in 2(m) x 2(n); warp tile 64x64 via 4x8 m16n8k8 fragments.
// Dynamic smem: As[2][128][36] | Bs[2][32][136] | ps[128][2] ps2[128][2] pmv[128] prv[128]
// EPI: 0 = plain store, 1 = bias+relu store, 2 = fused residual+bias+LayerNorm into C (Ndim=128,n0=0)
#define AS_OFF   0
#define BS_OFF   (2*128*36)                 // 9216
#define PS_OFF   (BS_OFF + 2*32*136)        // 9216+8704 = 17920
#define PS2_OFF  (PS_OFF + 256)
#define PMV_OFF  (PS2_OFF + 256)
#define PRV_OFF  (PMV_OFF + 128)
#define GEMM_SMEM ((PRV_OFF + 128) * 4)     // 74752 bytes

template<int EPI>
__device__ __forceinline__ void mma_core(const float* __restrict__ A,
                                         const float* __restrict__ W,
                                         float* __restrict__ C,
                                         const float* __restrict__ bias,
                                         const float* __restrict__ gamma,
                                         const float* __restrict__ beta,
                                         int Ndim, int Kdim, int m0, int n0)
{
    extern __shared__ float smg[];
    float* As  = smg + AS_OFF;    // [buf][m][36]
    float* Bs  = smg + BS_OFF;    // [buf][k][136]
    float* ps  = smg + PS_OFF;    // [128][2]
    float* ps2 = smg + PS2_OFF;   // [128][2]
    float* pmv = smg + PMV_OFF;
    float* prv = smg + PRV_OFF;

    const int t    = threadIdx.x;
    const int lane = t & 31;
    const int w    = t >> 5;
    const int wm   = w >> 1;            // 0..1
    const int wn   = w & 1;             // 0..1
    const int g    = lane >> 2;         // 0..7
    const int tig  = lane & 3;          // 0..3

    float c_[4][8][4];
    #pragma unroll
    for (int mi = 0; mi < 4; mi++)
        #pragma unroll
        for (int ni = 0; ni < 8; ni++)
            #pragma unroll
            for (int r = 0; r < 4; r++) c_[mi][ni][r] = 0.f;

    auto issue = [&](int kb, int buf) {
        float* Ab = As + buf*128*36;
        float* Bb_ = Bs + buf*32*136;
        #pragma unroll
        for (int q = 0; q < 8; q++) {          // A tile: 128 rows x 32k = 1024 float4
            int idx = q*128 + t;
            int m = idx >> 3, f4 = idx & 7;
            cp16(Ab + m*36 + f4*4, A + (size_t)(m0+m)*Kdim + kb*32 + f4*4);
        }
        #pragma unroll
        for (int q = 0; q < 8; q++) {          // B tile: 32k x 128n = 1024 float4
            int idx = q*128 + t;
            int k = idx >> 5, n4 = idx & 31;
            cp16(Bb_ + k*136 + n4*4, W + (size_t)(kb*32+k)*Ndim + n0 + n4*4);
        }
        cp_commit();
    };

    issue(0, 0);
    const int nk = Kdim >> 5;
    for (int kb = 0; kb < nk; kb++) {
        const int cur = kb & 1;
        cp_wait<0>();
        __syncthreads();
        if (kb + 1 < nk) issue(kb+1, cur ^ 1);
        float* Ab = As + cur*128*36;
        float* Bb_ = Bs + cur*32*136;

        #pragma unroll
        for (int k8 = 0; k8 < 32; k8 += 8) {
            uint32_t af[4][4];
            #pragma unroll
            for (int mi = 0; mi < 4; mi++) {
                int mm = wm*64 + mi*16 + g;
                af[mi][0] = __float_as_uint(Ab[(mm  )*36 + k8+tig]);
                af[mi][1] = __float_as_uint(Ab[(mm+8)*36 + k8+tig]);
                af[mi][2] = __float_as_uint(Ab[(mm  )*36 + k8+tig+4]);
                af[mi][3] = __float_as_uint(Ab[(mm+8)*36 + k8+tig+4]);
            }
            uint32_t bf[8][2];
            #pragma unroll
            for (int ni = 0; ni < 8; ni++) {
                int nn = wn*64 + ni*8 + g;
                bf[ni][0] = __float_as_uint(Bb_[(k8+tig  )*136 + nn]);
                bf[ni][1] = __float_as_uint(Bb_[(k8+tig+4)*136 + nn]);
            }
            #pragma unroll
            for (int mi = 0; mi < 4; mi++)
                #pragma unroll
                for (int ni = 0; ni < 8; ni++)
                    mma8(c_[mi][ni], af[mi], bf[ni][0], bf[ni][1]);
        }
    }

    if (EPI == 2) {
        // fused residual + bias + LayerNorm; Ndim==128, n0==0, C == tok (also residual)
        float bi[8][2], gm[8][2], bt[8][2];
        #pragma unroll
        for (int ni = 0; ni < 8; ni++) {
            int col = wn*64 + ni*8 + 2*tig;
            float2 v;
            v = *(const float2*)(bias  + col); bi[ni][0] = v.x; bi[ni][1] = v.y;
            v = *(const float2*)(gamma + col); gm[ni][0] = v.x; gm[ni][1] = v.y;
            v = *(const float2*)(beta  + col); bt[ni][0] = v.x; bt[ni][1] = v.y;
        }
        #pragma unroll
        for (int mi = 0; mi < 4; mi++) {
            #pragma unroll
            for (int hh = 0; hh < 2; hh++) {
                int lrow = wm*64 + mi*16 + g + hh*8;
                size_t m = (size_t)(m0 + lrow);
                float s = 0.f, s2 = 0.f;
                #pragma unroll
                for (int ni = 0; ni < 8; ni++) {
                    int col = wn*64 + ni*8 + 2*tig;
                    float2 res = *(const float2*)(C + m*128 + col);
                    float v0 = c_[mi][ni][hh*2+0] + res.x + bi[ni][0];
                    float v1 = c_[mi][ni][hh*2+1] + res.y + bi[ni][1];
                    c_[mi][ni][hh*2+0] = v0;
                    c_[mi][ni][hh*2+1] = v1;
                    s += v0 + v1; s2 += v0*v0 + v1*v1;
                }
                // quad reduce over tig (lanes g*4+tig)
                s  += __shfl_xor_sync(0xffffffffu, s,  1);
                s  += __shfl_xor_sync(0xffffffffu, s,  2);
                s2 += __shfl_xor_sync(0xffffffffu, s2, 1);
                s2 += __shfl_xor_sync(0xffffffffu, s2, 2);
                if (tig == 0) { ps[lrow*2 + wn] = s; ps2[lrow*2 + wn] = s2; }
            }
        }
        __syncthreads();
        if (t < 128) {
            float s = ps[t*2+0] + ps[t*2+1];
            float s2 = ps2[t*2+0] + ps2[t*2+1];
            float mean = s * (1.f/128.f);
            float var  = s2 * (1.f/128.f) - mean*mean;
            pmv[t] = mean;
            prv[t] = rsqrtf(var + 1e-5f);
        }
        __syncthreads();
        #pragma unroll
        for (int mi = 0; mi < 4; mi++) {
            #pragma unroll
            for (int hh = 0; hh < 2; hh++) {
                int lrow = wm*64 + mi*16 + g + hh*8;
                size_t m = (size_t)(m0 + lrow);
                float mean = pmv[lrow], r = prv[lrow];
                #pragma unroll
                for (int ni = 0; ni < 8; ni++) {
                    int col = wn*64 + ni*8 + 2*tig;
                    float2 o;
                    o.x = (c_[mi][ni][hh*2+0] - mean) * r * gm[ni][0] + bt[ni][0];
                    o.y = (c_[mi][ni][hh*2+1] - mean) * r * gm[ni][1] + bt[ni][1];
                    *(float2*)(C + m*128 + col) = o;
                }
            }
        }
    } else {
        #pragma unroll
        for (int mi = 0; mi < 4; mi++) {
            #pragma unroll
            for (int hh = 0; hh < 2; hh++) {
                size_t m = (size_t)(m0 + wm*64 + mi*16 + g + hh*8);
                #pragma unroll
                for (int ni = 0; ni < 8; ni++) {
                    int col = n0 + wn*64 + ni*8 + 2*tig;
                    float v0 = c_[mi][ni][hh*2+0];
                    float v1 = c_[mi][ni][hh*2+1];
                    if (EPI == 1) {
                        v0 = fmaxf(v0 + bias[col],   0.f);
                        v1 = fmaxf(v1 + bias[col+1], 0.f);
                    }
                    float2 o; o.x = v0; o.y = v1;
                    *(float2*)(C + m * Ndim + col) = o;
                }
            }
        }
    }
}

struct Ptr8 { const float* w[4]; float* c[4]; };

__global__ void __launch_bounds__(128, 2) sgemm4_kernel(const float* A, Ptr8 p)
{
    mma_core<0>(A, p.w[blockIdx.z], p.c[blockIdx.z], nullptr, nullptr, nullptr,
                128, 128, blockIdx.y * 128, 0);
}
__global__ void __launch_bounds__(128, 2) sgemm_bias_relu_kernel(const float* A, const float* W,
                                                                 float* C, const float* bias,
                                                                 int Ndim, int Kdim)
{
    mma_core<1>(A, W, C, bias, nullptr, nullptr, Ndim, Kdim,
                blockIdx.y * 128, blockIdx.x * 128);
}
__global__ void __launch_bounds__(128, 2) sgemm_ln_kernel(const float* A, const float* W,
                                                          float* TOK, const float* bias,
                                                          const float* gamma, const float* beta,
                                                          int Kdim)
{
    mma_core<2>(A, W, TOK, bias, gamma, beta, 128, Kdim, blockIdx.y * 128, 0);
}

// ---------------- attention scores: s[b,h,l,i,j] = Q_l @ K_l^T / sqrt(DH) ----------------
__global__ void __launch_bounds__(256) scores_kernel()
{
    int lin = blockIdx.x;          // (b,h,l)
    int l = lin & 63, h = (lin >> 6) & 3, b = lin >> 8;
    __shared__ float Qs[32][68];   // [d][i]
    __shared__ float Ks[32][68];   // [d][j]
    for (int e = threadIdx.x; e < 2048; e += 256) {
        int i = e >> 5, d = e & 31;
        Qs[d][i] = g_q[((size_t)((b*64+i)*64 + l))*128 + h*32 + d];
        Ks[d][i] = g_k[((size_t)((b*64+l)*64 + i))*128 + h*32 + d];
    }
    __syncthreads();
    int ti = threadIdx.x >> 4, tj = threadIdx.x & 15;
    int i0 = ti*4, j0 = tj*4;
    float acc[4][4];
    #pragma unroll
    for (int a = 0; a < 4; a++)
        #pragma unroll
        for (int c = 0; c < 4; c++) acc[a][c] = 0.f;
    #pragma unroll
    for (int d = 0; d < 32; d++) {
        float4 ra = *(const float4*)&Qs[d][i0];
        float4 rb = *(const float4*)&Ks[d][j0];
        float A[4] = {ra.x, ra.y, ra.z, ra.w};
        float Bv[4] = {rb.x, rb.y, rb.z, rb.w};
        #pragma unroll
        for (int ii = 0; ii < 4; ii++)
            #pragma unroll
            for (int jj = 0; jj < 4; jj++)
                acc[ii][jj] += A[ii] * Bv[jj];
    }
    const float isc = 0.17677669529663687f;   // 1/sqrt(32)
    float* sp = g_s + ((size_t)((b*4+h)*64 + l)) * 4096;
    #pragma unroll
    for (int ii = 0; ii < 4; ii++) {
        float4 v = make_float4(acc[ii][0]*isc, acc[ii][1]*isc, acc[ii][2]*isc, acc[ii][3]*isc);
        *(float4*)(sp + (i0+ii)*64 + j0) = v;
    }
}

// ---------------- combine + fused softmax over l ----------------
// o[b,i,j,h,d] = sum_l softmax_l(s)[b,h,l,i,j] * v1[b,i,l,h,d] * v2[b,l,j,h,d]
// i-tiled by 4. Thread map: t = j*8 + dg. v2 from gmem with depth-2 register ring; l unrolled x2.
// dyn smem: a4[4][64][64] | v1s[4][64][32] | invs[4][64]
#define CMB_SMEM ((16384 + 8192 + 256) * 4)
__global__ void __launch_bounds__(512, 2) combine_kernel()
{
    extern __shared__ float smc[];
    float* a4   = smc;            // [ii*4096 + l*64 + j]  raw s -> exp(s - max)
    float* v1s  = smc + 16384;    // [ii*2048 + l*32 + d]
    float* invs = smc + 24576;    // [ii*64 + j] = 1/sum

    int lin = blockIdx.x;        // (b,h,i4)
    int i4 = lin & 15, h = (lin >> 4) & 3, b = lin >> 6;
    int t = threadIdx.x;
    int j = t >> 3, dg = t & 7;  // dg 0..7, 4 d's each

    const float* abase = g_s + ((size_t)(b*4+h))*262144;
    for (int e = t; e < 16384; e += 512) {
        int ii = e >> 12, l = (e >> 6) & 63, jj = e & 63;
        a4[ii*4096 + l*64 + jj] = abase[(size_t)l*4096 + (i4*4+ii)*64 + jj];
    }
    for (int e = t; e < 8192; e += 512) {
        int ii = e >> 11, l = (e >> 5) & 63, d = e & 31;
        v1s[ii*2048 + l*32 + d] = g_v1[((size_t)((b*64+i4*4+ii)*64 + l))*128 + h*32 + d];
    }
    __syncthreads();   // a4/v1s visible

    // ---- softmax over l for each (ii, j): 2 threads per column (halves of l) ----
    {
        int col = t >> 1, half = t & 1;     // col 0..255
        int cii = col >> 6, cj = col & 63;
        float* sp = a4 + cii*4096 + cj + half*32*64;
        float mx = -1e30f;
        #pragma unroll 4
        for (int l = 0; l < 32; l++) mx = fmaxf(mx, sp[l*64]);
        mx = fmaxf(mx, __shfl_xor_sync(0xffffffffu, mx, 1));
        float sum = 0.f;
        #pragma unroll 4
        for (int l = 0; l < 32; l++) { float e = __expf(sp[l*64] - mx); sp[l*64] = e; sum += e; }
        sum += __shfl_xor_sync(0xffffffffu, sum, 1);
        if (half == 0) invs[col] = 1.f / sum;
    }
    __syncthreads();

    float acc[4][4];
    #pragma unroll
    for (int ii = 0; ii < 4; ii++)
        #pragma unroll
        for (int k = 0; k < 4; k++) acc[ii][k] = 0.f;

    // v2 pointer for this thread's (j, dg): advance by l (stride 64*128 floats)
    const float* v2p = g_v2 + ((size_t)(b*64)*64 + j)*128 + h*32 + dg*4;
    const size_t v2step = (size_t)64*128;

    float4 nv0 = *(const float4*)(v2p);              // prefetch l=0
    float4 nv1 = *(const float4*)(v2p + v2step);     // prefetch l=1
    #pragma unroll 2
    for (int l = 0; l < 64; l += 2) {
        float4 va = nv0, vb = nv1;
        if (l + 2 < 64) nv0 = *(const float4*)(v2p + (size_t)(l+2)*v2step);
        if (l + 3 < 64) nv1 = *(const float4*)(v2p + (size_t)(l+3)*v2step);
        #pragma unroll
        for (int ii = 0; ii < 4; ii++) {
            float av = a4[ii*4096 + l*64 + j];
            const float4 v1v = *(const float4*)&v1s[ii*2048 + l*32 + dg*4];
            acc[ii][0] += av * v1v.x * va.x;
            acc[ii][1] += av * v1v.y * va.y;
            acc[ii][2] += av * v1v.z * va.z;
            acc[ii][3] += av * v1v.w * va.w;
        }
        #pragma unroll
        for (int ii = 0; ii < 4; ii++) {
            float av = a4[ii*4096 + (l+1)*64 + j];
            const float4 v1v = *(const float4*)&v1s[ii*2048 + (l+1)*32 + dg*4];
            acc[ii][0] += av * v1v.x * vb.x;
            acc[ii][1] += av * v1v.y * vb.y;
            acc[ii][2] += av * v1v.z * vb.z;
            acc[ii][3] += av * v1v.w * vb.w;
        }
    }

    float inv4[4];
    #pragma unroll
    for (int ii = 0; ii < 4; ii++) inv4[ii] = invs[ii*64 + j];

    #pragma unroll
    for (int ii = 0; ii < 4; ii++) {
        int i = i4*4 + ii;
        float4 v = make_float4(acc[ii][0]*inv4[ii], acc[ii][1]*inv4[ii],
                               acc[ii][2]*inv4[ii], acc[ii][3]*inv4[ii]);
        *(float4*)(g_o + ((size_t)((b*64+i)*64 + j))*128 + h*32 + dg*4) = v;
    }
}

// ---------------- final head: out[b,n] = tok[b,n,n,:] @ Wout + bout ----------------
__global__ void out_kernel(const float* __restrict__ Wout, const float* __restrict__ bout,
                           float* __restrict__ out)
{
    int bn = blockIdx.x, d = threadIdx.x;
    int b = bn >> 6, n = bn & 63;
    float v = g_tok[((size_t)((b*64+n)*64 + n))*128 + d] * Wout[d];
    #pragma unroll
    for (int o = 16; o; o >>= 1) v += __shfl_xor_sync(0xffffffffu, v, o);
    __shared__ float ws[4];
    if ((d & 31) == 0) ws[d >> 5] = v;
    __syncthreads();
    if (d == 0) out[bn] = ws[0] + ws[1] + ws[2] + ws[3] + bout[0];
}

// ---------------- host orchestration ----------------
extern "C" void kernel_launch(void* const* d_in, const int* in_sizes, int n_in,
                              void* d_out, int out_size)
{
    const float* x    = (const float*)d_in[0];
    const float* ea   = (const float*)d_in[1];
    const int*   mask = (const int*)d_in[2];
    const float* nW   = (const float*)d_in[3];
    const float* nb   = (const float*)d_in[4];
    const float* eW   = (const float*)d_in[5];
    const float* eb   = (const float*)d_in[6];
    const float* noe  = (const float*)d_in[7];
    const float* Wq   = (const float*)d_in[8];
    const float* Wk   = (const float*)d_in[9];
    const float* Wv1  = (const float*)d_in[10];
    const float* Wv2  = (const float*)d_in[11];
    const float* Wo   = (const float*)d_in[12];
    const float* bo   = (const float*)d_in[13];
    const float* ln1g = (const float*)d_in[14];
    const float* ln1b = (const float*)d_in[15];
    const float* W1   = (const float*)d_in[16];
    const float* b1   = (const float*)d_in[17];
    const float* W2   = (const float*)d_in[18];
    const float* b2   = (const float*)d_in[19];
    const float* ln2g = (const float*)d_in[20];
    const float* ln2b = (const float*)d_in[21];
    const float* Wout = (const float*)d_in[22];
    const float* bout = (const float*)d_in[23];
    float* out = (float*)d_out;

    float *tok, *q, *k, *v1, *v2, *o, *hid;
    cudaGetSymbolAddress((void**)&tok, g_tok);
    cudaGetSymbolAddress((void**)&q,   g_q);
    cudaGetSymbolAddress((void**)&k,   g_k);
    cudaGetSymbolAddress((void**)&v1,  g_v1);
    cudaGetSymbolAddress((void**)&v2,  g_v2);
    cudaGetSymbolAddress((void**)&o,   g_o);
    cudaGetSymbolAddress((void**)&hid, g_hid);

    cudaFuncSetAttribute(combine_kernel, cudaFuncAttributeMaxDynamicSharedMemorySize, CMB_SMEM);
    cudaFuncSetAttribute(sgemm4_kernel, cudaFuncAttributeMaxDynamicSharedMemorySize, GEMM_SMEM);
    cudaFuncSetAttribute(sgemm_bias_relu_kernel, cudaFuncAttributeMaxDynamicSharedMemorySize, GEMM_SMEM);
    cudaFuncSetAttribute(sgemm_ln_kernel, cudaFuncAttributeMaxDynamicSharedMemorySize, GEMM_SMEM);

    embed_kernel<<<Mm, 128>>>(x, ea, mask, nW, nb, eW, eb, noe);

    for (int l = 0; l < Llay; l++) {
        Ptr8 p;
        p.w[0] = Wq  + (size_t)l*128*128;
        p.w[1] = Wk  + (size_t)l*128*128;
        p.w[2] = Wv1 + (size_t)l*128*128;
        p.w[3] = Wv2 + (size_t)l*128*128;
        p.c[0] = q; p.c[1] = k; p.c[2] = v1; p.c[3] = v2;
        sgemm4_kernel<<<dim3(1, Mm/128, 4), 128, GEMM_SMEM>>>(tok, p);

        scores_kernel <<<Bb*Hh*Nn, 256>>>();
        combine_kernel<<<Bb*Hh*(Nn/4), 512, CMB_SMEM>>>();

        // tok = LN(tok + o@Wo + bo)   (fused epilogue)
        sgemm_ln_kernel<<<dim3(1, Mm/128), 128, GEMM_SMEM>>>(o, Wo + (size_t)l*128*128, tok,
                                                  bo + l*128, ln1g + l*128, ln1b + l*128, 128);

        // ff
        sgemm_bias_relu_kernel<<<dim3(FFf/128, Mm/128), 128, GEMM_SMEM>>>(tok, W1 + (size_t)l*128*512,
                                                               hid, b1 + l*512, 512, 128);
        // tok = LN(tok + hid@W2 + b2) (fused epilogue)
        sgemm_ln_kernel<<<dim3(1, Mm/128), 128, GEMM_SMEM>>>(hid, W2 + (size_t)l*512*128, tok,
                                                  b2 + l*128, ln2g + l*128, ln2b + l*128, 512);
    }

    out_kernel<<<Bb*Nn, 128>>>(Wout, bout, out);
}

// round 9
// speedup vs baseline: 1.4083x; 1.0048x over previous
#include <cuda_runtime.h>
#include <math.h>
#include <stdint.h>

// Problem constants
#define Bb   8
#define Nn   64
#define Dd   128
#define Hh   4
#define DHh  32
#define Llay 3
#define FFf  512
#define Mm   (Bb*Nn*Nn)   // 32768 tokens

// ---------------- scratch (device globals; no runtime allocation) ----------------
__device__ float g_tok[Mm*Dd];            // 16 MB
__device__ float g_q  [Mm*Dd];
__device__ float g_k  [Mm*Dd];
__device__ float g_v1 [Mm*Dd];
__device__ float g_v2 [Mm*Dd];
__device__ float g_s  [Bb*Hh*Nn*Nn*Nn];   // [b,h,l,i,j]  33.5 MB
__device__ float g_o  [Mm*Dd];
__device__ float g_hid[Mm*FFf];           // 64 MB

// ---------------- helpers ----------------
__device__ __forceinline__ void mma8(float* c, const uint32_t* a, uint32_t b0, uint32_t b1) {
    asm volatile("mma.sync.aligned.m16n8k8.row.col.f32.tf32.tf32.f32 "
                 "{%0,%1,%2,%3}, {%4,%5,%6,%7}, {%8,%9}, {%0,%1,%2,%3};"
                 : "+f"(c[0]), "+f"(c[1]), "+f"(c[2]), "+f"(c[3])
                 : "r"(a[0]), "r"(a[1]), "r"(a[2]), "r"(a[3]), "r"(b0), "r"(b1));
}
__device__ __forceinline__ void cp16(void* dst_smem, const void* src) {
    uint32_t d = (uint32_t)__cvta_generic_to_shared(dst_smem);
    asm volatile("cp.async.cg.shared.global [%0], [%1], 16;" :: "r"(d), "l"(src) : "memory");
}
__device__ __forceinline__ void cp_commit() {
    asm volatile("cp.async.commit_group;" ::: "memory");
}
template<int N>
__device__ __forceinline__ void cp_wait() {
    asm volatile("cp.async.wait_group %0;" :: "n"(N) : "memory");
}

// ---------------- embedding ----------------
__global__ void embed_kernel(const float* __restrict__ x, const float* __restrict__ ea,
                             const int* __restrict__ mask,
                             const float* __restrict__ nW, const float* __restrict__ nb,
                             const float* __restrict__ eW, const float* __restrict__ eb,
                             const float* __restrict__ noe)
{
    int m = blockIdx.x;           // token index (b,i,j)
    int d = threadIdx.x;          // 0..127
    int b = m >> 12;
    int i = (m >> 6) & 63;
    int j = m & 63;
    __shared__ float in_s[16];
    if (i == j) {
        if (d < 16) in_s[d] = x[(b*64+i)*16 + d];
        __syncthreads();
        float acc = nb[d];
        #pragma unroll
        for (int k = 0; k < 16; k++) acc += in_s[k] * nW[k*128 + d];
        g_tok[(size_t)m*128 + d] = acc;
    } else if (mask[m] != 0) {
        if (d < 8) in_s[d] = ea[(size_t)m*8 + d];
        __syncthreads();
        float acc = eb[d];
        #pragma unroll
        for (int k = 0; k < 8; k++) acc += in_s[k] * eW[k*128 + d];
        g_tok[(size_t)m*128 + d] = acc;
    } else {
        g_tok[(size_t)m*128 + d] = noe[d];
    }
}

// ---------------- TF32 tensor-core GEMM: 128x128 CTA tile, BK=32, cp.async double-buffer ----------------
// 128 threads = 4 warps in 2(m) x 2(n); warp tile 64x64 via 4x8 m16n8k8 fragments.
// Dynamic smem: As[2][128][36] | Bs[2][32][136] | ps[128][2] ps2[128][2] pmv[128] prv[128]
// EPI: 0 = plain store, 1 = bias+relu store, 2 = fused residual+bias+LayerNorm into C (Ndim=128,n0=0)
#define AS_OFF   0
#define BS_OFF   (2*128*36)                 // 9216
#define PS_OFF   (BS_OFF + 2*32*136)        // 9216+8704 = 17920
#define PS2_OFF  (PS_OFF + 256)
#define PMV_OFF  (PS2_OFF + 256)
#define PRV_OFF  (PMV_OFF + 128)
#define GEMM_SMEM ((PRV_OFF + 128) * 4)     // 74752 bytes

template<int EPI>
__device__ __forceinline__ void mma_core(const float* __restrict__ A,
                                         const float* __restrict__ W,
                                         float* __restrict__ C,
                                         const float* __restrict__ bias,
                                         const float* __restrict__ gamma,
                                         const float* __restrict__ beta,
                                         int Ndim, int Kdim, int m0, int n0)
{
    extern __shared__ float smg[];
    float* As  = smg + AS_OFF;    // [buf][m][36]
    float* Bs  = smg + BS_OFF;    // [buf][k][136]
    float* ps  = smg + PS_OFF;    // [128][2]
    float* ps2 = smg + PS2_OFF;   // [128][2]
    float* pmv = smg + PMV_OFF;
    float* prv = smg + PRV_OFF;

    const int t    = threadIdx.x;
    const int lane = t & 31;
    const int w    = t >> 5;
    const int wm   = w >> 1;            // 0..1
    const int wn   = w & 1;             // 0..1
    const int g    = lane >> 2;         // 0..7
    const int tig  = lane & 3;          // 0..3

    float c_[4][8][4];
    #pragma unroll
    for (int mi = 0; mi < 4; mi++)
        #pragma unroll
        for (int ni = 0; ni < 8; ni++)
            #pragma unroll
            for (int r = 0; r < 4; r++) c_[mi][ni][r] = 0.f;

    auto issue = [&](int kb, int buf) {
        float* Ab = As + buf*128*36;
        float* Bb_ = Bs + buf*32*136;
        #pragma unroll
        for (int q = 0; q < 8; q++) {          // A tile: 128 rows x 32k = 1024 float4
            int idx = q*128 + t;
            int m = idx >> 3, f4 = idx & 7;
            cp16(Ab + m*36 + f4*4, A + (size_t)(m0+m)*Kdim + kb*32 + f4*4);
        }
        #pragma unroll
        for (int q = 0; q < 8; q++) {          // B tile: 32k x 128n = 1024 float4
            int idx = q*128 + t;
            int k = idx >> 5, n4 = idx & 31;
            cp16(Bb_ + k*136 + n4*4, W + (size_t)(kb*32+k)*Ndim + n0 + n4*4);
        }
        cp_commit();
    };

    issue(0, 0);
    const int nk = Kdim >> 5;
    for (int kb = 0; kb < nk; kb++) {
        const int cur = kb & 1;
        cp_wait<0>();
        __syncthreads();
        if (kb + 1 < nk) issue(kb+1, cur ^ 1);
        float* Ab = As + cur*128*36;
        float* Bb_ = Bs + cur*32*136;

        #pragma unroll
        for (int k8 = 0; k8 < 32; k8 += 8) {
            uint32_t af[4][4];
            #pragma unroll
            for (int mi = 0; mi < 4; mi++) {
                int mm = wm*64 + mi*16 + g;
                af[mi][0] = __float_as_uint(Ab[(mm  )*36 + k8+tig]);
                af[mi][1] = __float_as_uint(Ab[(mm+8)*36 + k8+tig]);
                af[mi][2] = __float_as_uint(Ab[(mm  )*36 + k8+tig+4]);
                af[mi][3] = __float_as_uint(Ab[(mm+8)*36 + k8+tig+4]);
            }
            uint32_t bf[8][2];
            #pragma unroll
            for (int ni = 0; ni < 8; ni++) {
                int nn = wn*64 + ni*8 + g;
                bf[ni][0] = __float_as_uint(Bb_[(k8+tig  )*136 + nn]);
                bf[ni][1] = __float_as_uint(Bb_[(k8+tig+4)*136 + nn]);
            }
            #pragma unroll
            for (int mi = 0; mi < 4; mi++)
                #pragma unroll
                for (int ni = 0; ni < 8; ni++)
                    mma8(c_[mi][ni], af[mi], bf[ni][0], bf[ni][1]);
        }
    }

    if (EPI == 2) {
        // fused residual + bias + LayerNorm; Ndim==128, n0==0, C == tok (also residual)
        float bi[8][2], gm[8][2], bt[8][2];
        #pragma unroll
        for (int ni = 0; ni < 8; ni++) {
            int col = wn*64 + ni*8 + 2*tig;
            float2 v;
            v = *(const float2*)(bias  + col); bi[ni][0] = v.x; bi[ni][1] = v.y;
            v = *(const float2*)(gamma + col); gm[ni][0] = v.x; gm[ni][1] = v.y;
            v = *(const float2*)(beta  + col); bt[ni][0] = v.x; bt[ni][1] = v.y;
        }
        #pragma unroll
        for (int mi = 0; mi < 4; mi++) {
            #pragma unroll
            for (int hh = 0; hh < 2; hh++) {
                int lrow = wm*64 + mi*16 + g + hh*8;
                size_t m = (size_t)(m0 + lrow);
                float s = 0.f, s2 = 0.f;
                #pragma unroll
                for (int ni = 0; ni < 8; ni++) {
                    int col = wn*64 + ni*8 + 2*tig;
                    float2 res = *(const float2*)(C + m*128 + col);
                    float v0 = c_[mi][ni][hh*2+0] + res.x + bi[ni][0];
                    float v1 = c_[mi][ni][hh*2+1] + res.y + bi[ni][1];
                    c_[mi][ni][hh*2+0] = v0;
                    c_[mi][ni][hh*2+1] = v1;
                    s += v0 + v1; s2 += v0*v0 + v1*v1;
                }
                // quad reduce over tig (lanes g*4+tig)
                s  += __shfl_xor_sync(0xffffffffu, s,  1);
                s  += __shfl_xor_sync(0xffffffffu, s,  2);
                s2 += __shfl_xor_sync(0xffffffffu, s2, 1);
                s2 += __shfl_xor_sync(0xffffffffu, s2, 2);
                if (tig == 0) { ps[lrow*2 + wn] = s; ps2[lrow*2 + wn] = s2; }
            }
        }
        __syncthreads();
        if (t < 128) {
            float s = ps[t*2+0] + ps[t*2+1];
            float s2 = ps2[t*2+0] + ps2[t*2+1];
            float mean = s * (1.f/128.f);
            float var  = s2 * (1.f/128.f) - mean*mean;
            pmv[t] = mean;
            prv[t] = rsqrtf(var + 1e-5f);
        }
        __syncthreads();
        #pragma unroll
        for (int mi = 0; mi < 4; mi++) {
            #pragma unroll
            for (int hh = 0; hh < 2; hh++) {
                int lrow = wm*64 + mi*16 + g + hh*8;
                size_t m = (size_t)(m0 + lrow);
                float mean = pmv[lrow], r = prv[lrow];
                #pragma unroll
                for (int ni = 0; ni < 8; ni++) {
                    int col = wn*64 + ni*8 + 2*tig;
                    float2 o;
                    o.x = (c_[mi][ni][hh*2+0] - mean) * r * gm[ni][0] + bt[ni][0];
                    o.y = (c_[mi][ni][hh*2+1] - mean) * r * gm[ni][1] + bt[ni][1];
                    *(float2*)(C + m*128 + col) = o;
                }
            }
        }
    } else {
        #pragma unroll
        for (int mi = 0; mi < 4; mi++) {
            #pragma unroll
            for (int hh = 0; hh < 2; hh++) {
                size_t m = (size_t)(m0 + wm*64 + mi*16 + g + hh*8);
                #pragma unroll
                for (int ni = 0; ni < 8; ni++) {
                    int col = n0 + wn*64 + ni*8 + 2*tig;
                    float v0 = c_[mi][ni][hh*2+0];
                    float v1 = c_[mi][ni][hh*2+1];
                    if (EPI == 1) {
                        v0 = fmaxf(v0 + bias[col],   0.f);
                        v1 = fmaxf(v1 + bias[col+1], 0.f);
                    }
                    float2 o; o.x = v0; o.y = v1;
                    *(float2*)(C + m * Ndim + col) = o;
                }
            }
        }
    }
}

struct Ptr8 { const float* w[4]; float* c[4]; };

__global__ void __launch_bounds__(128, 2) sgemm4_kernel(const float* A, Ptr8 p)
{
    mma_core<0>(A, p.w[blockIdx.z], p.c[blockIdx.z], nullptr, nullptr, nullptr,
                128, 128, blockIdx.y * 128, 0);
}
__global__ void __launch_bounds__(128, 2) sgemm_bias_relu_kernel(const float* A, const float* W,
                                                                 float* C, const float* bias,
                                                                 int Ndim, int Kdim)
{
    mma_core<1>(A, W, C, bias, nullptr, nullptr, Ndim, Kdim,
                blockIdx.y * 128, blockIdx.x * 128);
}
__global__ void __launch_bounds__(128, 2) sgemm_ln_kernel(const float* A, const float* W,
                                                          float* TOK, const float* bias,
                                                          const float* gamma, const float* beta,
                                                          int Kdim)
{
    mma_core<2>(A, W, TOK, bias, gamma, beta, 128, Kdim, blockIdx.y * 128, 0);
}

// ---------------- attention scores: s[b,h,l,i,j] = Q_l @ K_l^T / sqrt(DH) ----------------
__global__ void __launch_bounds__(256) scores_kernel()
{
    int lin = blockIdx.x;          // (b,h,l)
    int l = lin & 63, h = (lin >> 6) & 3, b = lin >> 8;
    __shared__ float Qs[32][68];   // [d][i]
    __shared__ float Ks[32][68];   // [d][j]
    for (int e = threadIdx.x; e < 2048; e += 256) {
        int i = e >> 5, d = e & 31;
        Qs[d][i] = g_q[((size_t)((b*64+i)*64 + l))*128 + h*32 + d];
        Ks[d][i] = g_k[((size_t)((b*64+l)*64 + i))*128 + h*32 + d];
    }
    __syncthreads();
    int ti = threadIdx.x >> 4, tj = threadIdx.x & 15;
    int i0 = ti*4, j0 = tj*4;
    float acc[4][4];
    #pragma unroll
    for (int a = 0; a < 4; a++)
        #pragma unroll
        for (int c = 0; c < 4; c++) acc[a][c] = 0.f;
    #pragma unroll
    for (int d = 0; d < 32; d++) {
        float4 ra = *(const float4*)&Qs[d][i0];
        float4 rb = *(const float4*)&Ks[d][j0];
        float A[4] = {ra.x, ra.y, ra.z, ra.w};
        float Bv[4] = {rb.x, rb.y, rb.z, rb.w};
        #pragma unroll
        for (int ii = 0; ii < 4; ii++)
            #pragma unroll
            for (int jj = 0; jj < 4; jj++)
                acc[ii][jj] += A[ii] * Bv[jj];
    }
    const float isc = 0.17677669529663687f;   // 1/sqrt(32)
    float* sp = g_s + ((size_t)((b*4+h)*64 + l)) * 4096;
    #pragma unroll
    for (int ii = 0; ii < 4; ii++) {
        float4 v = make_float4(acc[ii][0]*isc, acc[ii][1]*isc, acc[ii][2]*isc, acc[ii][3]*isc);
        *(float4*)(sp + (i0+ii)*64 + j0) = v;
    }
}

// ---------------- combine + fused softmax over l ----------------
// o[b,i,j,h,d] = sum_l softmax_l(s)[b,h,l,i,j] * v1[b,i,l,h,d] * v2[b,l,j,h,d]
// i-tiled by 4. Thread map: t = j*8 + dg. v2 from gmem with depth-2 register ring; l unrolled x2.
// a4 stored ii-INNERMOST: a4[l*256 + j*4 + ii] -> the 4 ii values are one float4 (1 LDS.128/l).
// dyn smem: a4[64][64][4] | v1s[4][64][32] | invs[64][4]
#define CMB_SMEM ((16384 + 8192 + 256) * 4)
__global__ void __launch_bounds__(512, 2) combine_kernel()
{
    extern __shared__ float smc[];
    float* a4   = smc;            // [l*256 + j*4 + ii]  raw s -> exp(s - max)
    float* v1s  = smc + 16384;    // [ii*2048 + l*32 + d]
    float* invs = smc + 24576;    // [j*4 + ii] = 1/sum

    int lin = blockIdx.x;        // (b,h,i4)
    int i4 = lin & 15, h = (lin >> 4) & 3, b = lin >> 6;
    int t = threadIdx.x;
    int j = t >> 3, dg = t & 7;  // dg 0..7, 4 d's each

    const float* abase = g_s + ((size_t)(b*4+h))*262144;
    for (int e = t; e < 16384; e += 512) {
        int ii = e >> 12, l = (e >> 6) & 63, jj = e & 63;
        a4[l*256 + jj*4 + ii] = abase[(size_t)l*4096 + (i4*4+ii)*64 + jj];
    }
    for (int e = t; e < 8192; e += 512) {
        int ii = e >> 11, l = (e >> 5) & 63, d = e & 31;
        v1s[ii*2048 + l*32 + d] = g_v1[((size_t)((b*64+i4*4+ii)*64 + l))*128 + h*32 + d];
    }
    __syncthreads();   // a4/v1s visible

    // ---- softmax over l for each (ii, j): 2 threads per column (halves of l) ----
    {
        int col = t >> 1, half = t & 1;     // col 0..255 -> (j = col>>2, ii = col&3)
        float* sp = a4 + col + half*32*256;
        float mx = -1e30f;
        #pragma unroll 4
        for (int l = 0; l < 32; l++) mx = fmaxf(mx, sp[l*256]);
        mx = fmaxf(mx, __shfl_xor_sync(0xffffffffu, mx, 1));
        float sum = 0.f;
        #pragma unroll 4
        for (int l = 0; l < 32; l++) { float e = __expf(sp[l*256] - mx); sp[l*256] = e; sum += e; }
        sum += __shfl_xor_sync(0xffffffffu, sum, 1);
        if (half == 0) invs[col] = 1.f / sum;
    }
    __syncthreads();

    float acc[4][4];
    #pragma unroll
    for (int ii = 0; ii < 4; ii++)
        #pragma unroll
        for (int k = 0; k < 4; k++) acc[ii][k] = 0.f;

    // v2 pointer for this thread's (j, dg): advance by l (stride 64*128 floats)
    const float* v2p = g_v2 + ((size_t)(b*64)*64 + j)*128 + h*32 + dg*4;
    const size_t v2step = (size_t)64*128;

    float4 nv0 = *(const float4*)(v2p);              // prefetch l=0
    float4 nv1 = *(const float4*)(v2p + v2step);     // prefetch l=1
    #pragma unroll 2
    for (int l = 0; l < 64; l += 2) {
        float4 va = nv0, vb = nv1;
        if (l + 2 < 64) nv0 = *(const float4*)(v2p + (size_t)(l+2)*v2step);
        if (l + 3 < 64) nv1 = *(const float4*)(v2p + (size_t)(l+3)*v2step);
        {
            float4 av4 = *(const float4*)&a4[l*256 + j*4];
            float aa[4] = {av4.x, av4.y, av4.z, av4.w};
            #pragma unroll
            for (int ii = 0; ii < 4; ii++) {
                const float4 v1v = *(const float4*)&v1s[ii*2048 + l*32 + dg*4];
                acc[ii][0] += aa[ii] * v1v.x * va.x;
                acc[ii][1] += aa[ii] * v1v.y * va.y;
                acc[ii][2] += aa[ii] * v1v.z * va.z;
                acc[ii][3] += aa[ii] * v1v.w * va.w;
            }
        }
        {
            float4 av4 = *(const float4*)&a4[(l+1)*256 + j*4];
            float aa[4] = {av4.x, av4.y, av4.z, av4.w};
            #pragma unroll
            for (int ii = 0; ii < 4; ii++) {
                const float4 v1v = *(const float4*)&v1s[ii*2048 + (l+1)*32 + dg*4];
                acc[ii][0] += aa[ii] * v1v.x * vb.x;
                acc[ii][1] += aa[ii] * v1v.y * vb.y;
                acc[ii][2] += aa[ii] * v1v.z * vb.z;
                acc[ii][3] += aa[ii] * v1v.w * vb.w;
            }
        }
    }

    float4 iv = *(const float4*)&invs[j*4];
    float inv4[4] = {iv.x, iv.y, iv.z, iv.w};

    #pragma unroll
    for (int ii = 0; ii < 4; ii++) {
        int i = i4*4 + ii;
        float4 v = make_float4(acc[ii][0]*inv4[ii], acc[ii][1]*inv4[ii],
                               acc[ii][2]*inv4[ii], acc[ii][3]*inv4[ii]);
        *(float4*)(g_o + ((size_t)((b*64+i)*64 + j))*128 + h*32 + dg*4) = v;
    }
}

// ---------------- final head: out[b,n] = tok[b,n,n,:] @ Wout + bout ----------------
__global__ void out_kernel(const float* __restrict__ Wout, const float* __restrict__ bout,
                           float* __restrict__ out)
{
    int bn = blockIdx.x, d = threadIdx.x;
    int b = bn >> 6, n = bn & 63;
    float v = g_tok[((size_t)((b*64+n)*64 + n))*128 + d] * Wout[d];
    #pragma unroll
    for (int o = 16; o; o >>= 1) v += __shfl_xor_sync(0xffffffffu, v, o);
    __shared__ float ws[4];
    if ((d & 31) == 0) ws[d >> 5] = v;
    __syncthreads();
    if (d == 0) out[bn] = ws[0] + ws[1] + ws[2] + ws[3] + bout[0];
}

// ---------------- host orchestration ----------------
extern "C" void kernel_launch(void* const* d_in, const int* in_sizes, int n_in,
                              void* d_out, int out_size)
{
    const float* x    = (const float*)d_in[0];
    const float* ea   = (const float*)d_in[1];
    const int*   mask = (const int*)d_in[2];
    const float* nW   = (const float*)d_in[3];
    const float* nb   = (const float*)d_in[4];
    const float* eW   = (const float*)d_in[5];
    const float* eb   = (const float*)d_in[6];
    const float* noe  = (const float*)d_in[7];
    const float* Wq   = (const float*)d_in[8];
    const float* Wk   = (const float*)d_in[9];
    const float* Wv1  = (const float*)d_in[10];
    const float* Wv2  = (const float*)d_in[11];
    const float* Wo   = (const float*)d_in[12];
    const float* bo   = (const float*)d_in[13];
    const float* ln1g = (const float*)d_in[14];
    const float* ln1b = (const float*)d_in[15];
    const float* W1   = (const float*)d_in[16];
    const float* b1   = (const float*)d_in[17];
    const float* W2   = (const float*)d_in[18];
    const float* b2   = (const float*)d_in[19];
    const float* ln2g = (const float*)d_in[20];
    const float* ln2b = (const float*)d_in[21];
    const float* Wout = (const float*)d_in[22];
    const float* bout = (const float*)d_in[23];
    float* out = (float*)d_out;

    float *tok, *q, *k, *v1, *v2, *o, *hid;
    cudaGetSymbolAddress((void**)&tok, g_tok);
    cudaGetSymbolAddress((void**)&q,   g_q);
    cudaGetSymbolAddress((void**)&k,   g_k);
    cudaGetSymbolAddress((void**)&v1,  g_v1);
    cudaGetSymbolAddress((void**)&v2,  g_v2);
    cudaGetSymbolAddress((void**)&o,   g_o);
    cudaGetSymbolAddress((void**)&hid, g_hid);

    cudaFuncSetAttribute(combine_kernel, cudaFuncAttributeMaxDynamicSharedMemorySize, CMB_SMEM);
    cudaFuncSetAttribute(sgemm4_kernel, cudaFuncAttributeMaxDynamicSharedMemorySize, GEMM_SMEM);
    cudaFuncSetAttribute(sgemm_bias_relu_kernel, cudaFuncAttributeMaxDynamicSharedMemorySize, GEMM_SMEM);
    cudaFuncSetAttribute(sgemm_ln_kernel, cudaFuncAttributeMaxDynamicSharedMemorySize, GEMM_SMEM);

    embed_kernel<<<Mm, 128>>>(x, ea, mask, nW, nb, eW, eb, noe);

    for (int l = 0; l < Llay; l++) {
        Ptr8 p;
        p.w[0] = Wq  + (size_t)l*128*128;
        p.w[1] = Wk  + (size_t)l*128*128;
        p.w[2] = Wv1 + (size_t)l*128*128;
        p.w[3] = Wv2 + (size_t)l*128*128;
        p.c[0] = q; p.c[1] = k; p.c[2] = v1; p.c[3] = v2;
        sgemm4_kernel<<<dim3(1, Mm/128, 4), 128, GEMM_SMEM>>>(tok, p);

        scores_kernel <<<Bb*Hh*Nn, 256>>>();
        combine_kernel<<<Bb*Hh*(Nn/4), 512, CMB_SMEM>>>();

        // tok = LN(tok + o@Wo + bo)   (fused epilogue)
        sgemm_ln_kernel<<<dim3(1, Mm/128), 128, GEMM_SMEM>>>(o, Wo + (size_t)l*128*128, tok,
                                                  bo + l*128, ln1g + l*128, ln1b + l*128, 128);

        // ff
        sgemm_bias_relu_kernel<<<dim3(FFf/128, Mm/128), 128, GEMM_SMEM>>>(tok, W1 + (size_t)l*128*512,
                                                               hid, b1 + l*512, 512, 128);
        // tok = LN(tok + hid@W2 + b2) (fused epilogue)
        sgemm_ln_kernel<<<dim3(1, Mm/128), 128, GEMM_SMEM>>>(hid, W2 + (size_t)l*512*128, tok,
                                                  b2 + l*128, ln2g + l*128, ln2b + l*128, 512);
    }

    out_kernel<<<Bb*Nn, 128>>>(Wout, bout, out);
}